// round 5
// baseline (speedup 1.0000x reference)
#include <cuda_runtime.h>
#include <stdint.h>

// QuantEmbedding fused: out[0:rows*dim] = gather(QIL_quantize(W,p,c), x),
// out[rows*dim] = s = 127/(c-p), out[rows*dim+1] = p = max(pp,0).
//
// Chunked kernel: each thread handles 4 consecutive float4s (64B) of one row.
// dim4 (=dim/4=192) is a multiple of 4, so a 4-aligned chunk never crosses a
// row boundary -> one token lookup + one row-div per thread, MLP=4.

__device__ __forceinline__ float qil_one(float w, float p, float s, float inv_s) {
    // |w|<p  =>  (|w|-p)*s < 0  =>  q <= 0, folded into the q>0 select.
    float aw = fabsf(w);
    float q  = rintf(fminf((aw - p) * s, 127.0f));
    float r  = copysignf(fmaf(q, inv_s, p), w);
    return (q > 0.0f) ? r : 0.0f;
}

__device__ __forceinline__ float4 qil_vec(float4 v, float p, float s, float inv_s) {
    float4 r;
    r.x = qil_one(v.x, p, s, inv_s);
    r.y = qil_one(v.y, p, s, inv_s);
    r.z = qil_one(v.z, p, s, inv_s);
    r.w = qil_one(v.w, p, s, inv_s);
    return r;
}

template <int DIM4>
__global__ __launch_bounds__(256)
void qembed_chunked_kernel(const int* __restrict__ x,
                           const float4* __restrict__ w4,
                           const float* __restrict__ pp,
                           const float* __restrict__ cp,
                           float4* __restrict__ out4,
                           long long n_float4,          // rows * DIM4
                           long long scalar_base, int n_scalars) {
    const float p = fmaxf(__ldg(&pp[0]), 0.0f);
    const float c = __ldg(&cp[0]);
    const float s = 127.0f / (c - p);
    const float inv_s = 1.0f / s;

    const long long base = ((long long)blockIdx.x * blockDim.x + threadIdx.x) * 4;
    if (base < n_float4) {
        const long long row = base / DIM4;            // compile-time const divisor
        const int       off = (int)(base - row * DIM4);
        const int       tok = __ldg(&x[row]);

        const float4* src = w4   + (long long)tok * DIM4 + off;
        float4*       dst = out4 + row * (long long)DIM4 + off;

        // 4 independent loads issued back-to-back (MLP=4)
        float4 v0 = __ldcs(&src[0]);
        float4 v1 = __ldcs(&src[1]);
        float4 v2 = __ldcs(&src[2]);
        float4 v3 = __ldcs(&src[3]);

        __stcs(&dst[0], qil_vec(v0, p, s, inv_s));
        __stcs(&dst[1], qil_vec(v1, p, s, inv_s));
        __stcs(&dst[2], qil_vec(v2, p, s, inv_s));
        __stcs(&dst[3], qil_vec(v3, p, s, inv_s));
    }

    if (blockIdx.x == 0 && threadIdx.x == 0 && n_scalars > 0) {
        float* out = (float*)out4;
        out[scalar_base] = s;
        if (n_scalars >= 2) out[scalar_base + 1] = p;
    }
}

// Generic fallback (arbitrary dim, incl. dim4 not divisible by 4): row/block.
__global__ __launch_bounds__(256)
void qembed_row_kernel(const int* __restrict__ x,
                       const float4* __restrict__ w4,
                       const float* __restrict__ pp,
                       const float* __restrict__ cp,
                       float4* __restrict__ out4,
                       int dim4, long long scalar_base, int n_scalars) {
    const int row = blockIdx.x;
    const int tok = __ldg(&x[row]);
    const float p = fmaxf(__ldg(&pp[0]), 0.0f);
    const float c = __ldg(&cp[0]);
    const float s = 127.0f / (c - p);
    const float inv_s = 1.0f / s;
    const long long src_base = (long long)tok * dim4;
    const long long dst_base = (long long)row * dim4;
    for (int j = threadIdx.x; j < dim4; j += blockDim.x) {
        float4 v = __ldcs(&w4[src_base + j]);
        __stcs(&out4[dst_base + j], qil_vec(v, p, s, inv_s));
    }
    if (blockIdx.x == 0 && threadIdx.x == 0 && n_scalars > 0) {
        float* out = (float*)out4;
        out[scalar_base] = s;
        if (n_scalars >= 2) out[scalar_base + 1] = p;
    }
}

extern "C" void kernel_launch(void* const* d_in, const int* in_sizes, int n_in,
                              void* d_out, int out_size) {
    const int*   x  = (const int*)d_in[0];          // [batch*seq] token ids
    const float* w  = (const float*)d_in[1];        // [vocab, dim] float32
    const float* pp = (const float*)d_in[2];        // [1]
    const float* cp = (const float*)d_in[3];        // [1]

    const int rows = in_sizes[0];                   // 16384

    // Derive dim and scalar-tail count from out_size.
    long long dim;
    int n_scalars;
    long long osz = (long long)out_size;
    if (rows > 0 && (osz - 2) > 0 && (osz - 2) % rows == 0) {
        dim = (osz - 2) / rows;  n_scalars = 2;     // expected: 768, 2
    } else if (rows > 0 && (osz - 1) > 0 && (osz - 1) % rows == 0) {
        dim = (osz - 1) / rows;  n_scalars = 1;
    } else {
        dim = (rows > 0) ? osz / rows : 0;  n_scalars = 0;
    }

    const int dim4 = (int)(dim / 4);
    const long long scalar_base = (long long)rows * dim;

    if (dim4 == 192 && (dim % 4) == 0) {
        const long long n_float4 = (long long)rows * 192;
        const long long n_chunks = n_float4 / 4;
        const int threads = 256;
        const int blocks  = (int)((n_chunks + threads - 1) / threads);
        qembed_chunked_kernel<192><<<blocks, threads>>>(
            x, (const float4*)w, pp, cp, (float4*)d_out,
            n_float4, scalar_base, n_scalars);
    } else if ((dim % 4) == 0) {
        int threads = dim4 < 256 ? ((dim4 + 31) / 32) * 32 : 256;
        if (threads < 32) threads = 32;
        qembed_row_kernel<<<rows, threads>>>(
            x, (const float4*)w, pp, cp, (float4*)d_out,
            dim4, scalar_base, n_scalars);
    }
}

// round 6
// speedup vs baseline: 1.5563x; 1.5563x over previous
#include <cuda_runtime.h>
#include <stdint.h>

// QuantEmbedding fused: out[0:rows*dim] = gather(QIL_quantize(W,p,c), x),
// out[rows*dim] = s = 127/(c-p), out[rows*dim+1] = p = max(pp,0).
//
// Multirow kernel: 192 threads/block (= dim4), block handles 4 rows.
// Thread tid <-> float4 tid of each row => warp-contiguous (4 lines/LDG.128),
// 4 independent row loads per thread => MLP=4, zero divisions.

__device__ __forceinline__ float qil_one(float w, float p, float s, float inv_s) {
    // |w|<p => (|w|-p)*s < 0 => q <= 0, folded into the q>0 select.
    float aw = fabsf(w);
    float q  = rintf(fminf((aw - p) * s, 127.0f));
    float r  = copysignf(fmaf(q, inv_s, p), w);
    return (q > 0.0f) ? r : 0.0f;
}

__device__ __forceinline__ float4 qil_vec(float4 v, float p, float s, float inv_s) {
    float4 r;
    r.x = qil_one(v.x, p, s, inv_s);
    r.y = qil_one(v.y, p, s, inv_s);
    r.z = qil_one(v.z, p, s, inv_s);
    r.w = qil_one(v.w, p, s, inv_s);
    return r;
}

template <int DIM4, int RPB>
__global__ __launch_bounds__(DIM4)
void qembed_multirow_kernel(const int* __restrict__ x,
                            const float4* __restrict__ w4,
                            const float* __restrict__ pp,
                            const float* __restrict__ cp,
                            float4* __restrict__ out4,
                            int rows, long long scalar_base, int n_scalars) {
    const int tid  = threadIdx.x;
    const int row0 = blockIdx.x * RPB;

    const float p = fmaxf(__ldg(&pp[0]), 0.0f);
    const float c = __ldg(&cp[0]);
    const float s = 127.0f / (c - p);
    const float inv_s = 1.0f / s;

    if (row0 + RPB <= rows) {
        int tok[RPB];
#pragma unroll
        for (int r = 0; r < RPB; r++) tok[r] = __ldg(&x[row0 + r]);

        float4 v[RPB];
#pragma unroll
        for (int r = 0; r < RPB; r++)       // 4 independent coalesced loads (MLP=4)
            v[r] = __ldcs(&w4[(long long)tok[r] * DIM4 + tid]);

#pragma unroll
        for (int r = 0; r < RPB; r++)
            __stcs(&out4[(long long)(row0 + r) * DIM4 + tid],
                   qil_vec(v[r], p, s, inv_s));
    } else {
        for (int r = 0; r < RPB; r++) {
            if (row0 + r >= rows) break;
            int tok = __ldg(&x[row0 + r]);
            float4 v = __ldcs(&w4[(long long)tok * DIM4 + tid]);
            __stcs(&out4[(long long)(row0 + r) * DIM4 + tid],
                   qil_vec(v, p, s, inv_s));
        }
    }

    if (blockIdx.x == 0 && tid == 0 && n_scalars > 0) {
        float* out = (float*)out4;
        out[scalar_base] = s;
        if (n_scalars >= 2) out[scalar_base + 1] = p;
    }
}

// Generic fallback (arbitrary dim divisible by 4): one row per block.
__global__ __launch_bounds__(256)
void qembed_row_kernel(const int* __restrict__ x,
                       const float4* __restrict__ w4,
                       const float* __restrict__ pp,
                       const float* __restrict__ cp,
                       float4* __restrict__ out4,
                       int dim4, long long scalar_base, int n_scalars) {
    const int row = blockIdx.x;
    const int tok = __ldg(&x[row]);
    const float p = fmaxf(__ldg(&pp[0]), 0.0f);
    const float c = __ldg(&cp[0]);
    const float s = 127.0f / (c - p);
    const float inv_s = 1.0f / s;
    const long long src_base = (long long)tok * dim4;
    const long long dst_base = (long long)row * dim4;
    for (int j = threadIdx.x; j < dim4; j += blockDim.x) {
        float4 v = __ldcs(&w4[src_base + j]);
        __stcs(&out4[dst_base + j], qil_vec(v, p, s, inv_s));
    }
    if (blockIdx.x == 0 && threadIdx.x == 0 && n_scalars > 0) {
        float* out = (float*)out4;
        out[scalar_base] = s;
        if (n_scalars >= 2) out[scalar_base + 1] = p;
    }
}

extern "C" void kernel_launch(void* const* d_in, const int* in_sizes, int n_in,
                              void* d_out, int out_size) {
    const int*   x  = (const int*)d_in[0];          // [batch*seq] token ids
    const float* w  = (const float*)d_in[1];        // [vocab, dim] float32
    const float* pp = (const float*)d_in[2];        // [1]
    const float* cp = (const float*)d_in[3];        // [1]

    const int rows = in_sizes[0];                   // 16384

    // Derive dim and scalar-tail count from out_size.
    long long dim;
    int n_scalars;
    long long osz = (long long)out_size;
    if (rows > 0 && (osz - 2) > 0 && (osz - 2) % rows == 0) {
        dim = (osz - 2) / rows;  n_scalars = 2;     // expected: 768, 2
    } else if (rows > 0 && (osz - 1) > 0 && (osz - 1) % rows == 0) {
        dim = (osz - 1) / rows;  n_scalars = 1;
    } else {
        dim = (rows > 0) ? osz / rows : 0;  n_scalars = 0;
    }

    const int dim4 = (int)(dim / 4);
    const long long scalar_base = (long long)rows * dim;

    if (dim4 == 192) {
        constexpr int RPB = 4;
        const int blocks = (rows + RPB - 1) / RPB;  // 4096
        qembed_multirow_kernel<192, RPB><<<blocks, 192>>>(
            x, (const float4*)w, pp, cp, (float4*)d_out,
            rows, scalar_base, n_scalars);
    } else if ((dim % 4) == 0 && dim4 > 0) {
        int threads = dim4 < 256 ? ((dim4 + 31) / 32) * 32 : 256;
        if (threads < 32) threads = 32;
        qembed_row_kernel<<<rows, threads>>>(
            x, (const float4*)w, pp, cp, (float4*)d_out,
            dim4, scalar_base, n_scalars);
    }
}

// round 7
// speedup vs baseline: 1.5702x; 1.0089x over previous
#include <cuda_runtime.h>
#include <stdint.h>

// QuantEmbedding fused: out[0:rows*dim] = gather(QIL_quantize(W,p,c), x),
// out[rows*dim] = s = 127/(c-p), out[rows*dim+1] = p = max(pp,0).
//
// Persistent grid-stride kernel, one wave. Block = 192 threads (= dim4),
// each group = 4 rows; thread tid <-> float4 tid of each row (warp-contiguous,
// MLP=4). Token ids for the NEXT group are prefetched while the current
// group's row data is loaded/quantized, hiding the dependent-gather latency.

__device__ __forceinline__ float qil_one(float w, float p, float s, float inv_s) {
    // |w|<p => (|w|-p)*s < 0 => q <= 0, folded into the q>0 select.
    float aw = fabsf(w);
    float q  = rintf(fminf((aw - p) * s, 127.0f));
    float r  = copysignf(fmaf(q, inv_s, p), w);
    return (q > 0.0f) ? r : 0.0f;
}

__device__ __forceinline__ float4 qil_vec(float4 v, float p, float s, float inv_s) {
    float4 r;
    r.x = qil_one(v.x, p, s, inv_s);
    r.y = qil_one(v.y, p, s, inv_s);
    r.z = qil_one(v.z, p, s, inv_s);
    r.w = qil_one(v.w, p, s, inv_s);
    return r;
}

template <int DIM4, int RPB>
__global__ __launch_bounds__(DIM4)
void qembed_persist_kernel(const int* __restrict__ x,
                           const float4* __restrict__ w4,
                           const float* __restrict__ pp,
                           const float* __restrict__ cp,
                           float4* __restrict__ out4,
                           int rows, int ngroups,
                           long long scalar_base, int n_scalars) {
    const int tid = threadIdx.x;

    const float p = fmaxf(__ldg(&pp[0]), 0.0f);
    const float c = __ldg(&cp[0]);
    const float s = 127.0f / (c - p);
    const float inv_s = 1.0f / s;

    if (blockIdx.x == 0 && tid == 0 && n_scalars > 0) {
        float* out = (float*)out4;
        out[scalar_base] = s;
        if (n_scalars >= 2) out[scalar_base + 1] = p;
    }

    int g = blockIdx.x;

    // Prefetch token ids for the first group.
    int tok[RPB];
    if (g < ngroups) {
        const int row0 = g * RPB;
#pragma unroll
        for (int r = 0; r < RPB; r++)
            tok[r] = (row0 + r < rows) ? __ldg(&x[row0 + r]) : 0;
    }

    while (g < ngroups) {
        const int row0 = g * RPB;
        const int gn   = g + gridDim.x;

        // Issue this group's 4 independent coalesced row loads (MLP=4).
        float4 v[RPB];
#pragma unroll
        for (int r = 0; r < RPB; r++)
            v[r] = __ldcs(&w4[(long long)tok[r] * DIM4 + tid]);

        // Prefetch next group's token ids while row data is in flight.
        int tokn[RPB];
        if (gn < ngroups) {
            const int nrow0 = gn * RPB;
#pragma unroll
            for (int r = 0; r < RPB; r++)
                tokn[r] = (nrow0 + r < rows) ? __ldg(&x[nrow0 + r]) : 0;
        }

#pragma unroll
        for (int r = 0; r < RPB; r++) {
            if (row0 + r < rows)
                __stcs(&out4[(long long)(row0 + r) * DIM4 + tid],
                       qil_vec(v[r], p, s, inv_s));
        }

#pragma unroll
        for (int r = 0; r < RPB; r++) tok[r] = tokn[r];
        g = gn;
    }
}

// Generic fallback (arbitrary dim divisible by 4): one row per block.
__global__ __launch_bounds__(256)
void qembed_row_kernel(const int* __restrict__ x,
                       const float4* __restrict__ w4,
                       const float* __restrict__ pp,
                       const float* __restrict__ cp,
                       float4* __restrict__ out4,
                       int dim4, long long scalar_base, int n_scalars) {
    const int row = blockIdx.x;
    const int tok = __ldg(&x[row]);
    const float p = fmaxf(__ldg(&pp[0]), 0.0f);
    const float c = __ldg(&cp[0]);
    const float s = 127.0f / (c - p);
    const float inv_s = 1.0f / s;
    const long long src_base = (long long)tok * dim4;
    const long long dst_base = (long long)row * dim4;
    for (int j = threadIdx.x; j < dim4; j += blockDim.x) {
        float4 v = __ldcs(&w4[src_base + j]);
        __stcs(&out4[dst_base + j], qil_vec(v, p, s, inv_s));
    }
    if (blockIdx.x == 0 && threadIdx.x == 0 && n_scalars > 0) {
        float* out = (float*)out4;
        out[scalar_base] = s;
        if (n_scalars >= 2) out[scalar_base + 1] = p;
    }
}

extern "C" void kernel_launch(void* const* d_in, const int* in_sizes, int n_in,
                              void* d_out, int out_size) {
    const int*   x  = (const int*)d_in[0];          // [batch*seq] token ids
    const float* w  = (const float*)d_in[1];        // [vocab, dim] float32
    const float* pp = (const float*)d_in[2];        // [1]
    const float* cp = (const float*)d_in[3];        // [1]

    const int rows = in_sizes[0];                   // 16384

    // Derive dim and scalar-tail count from out_size.
    long long dim;
    int n_scalars;
    long long osz = (long long)out_size;
    if (rows > 0 && (osz - 2) > 0 && (osz - 2) % rows == 0) {
        dim = (osz - 2) / rows;  n_scalars = 2;     // expected: 768, 2
    } else if (rows > 0 && (osz - 1) > 0 && (osz - 1) % rows == 0) {
        dim = (osz - 1) / rows;  n_scalars = 1;
    } else {
        dim = (rows > 0) ? osz / rows : 0;  n_scalars = 0;
    }

    const int dim4 = (int)(dim / 4);
    const long long scalar_base = (long long)rows * dim;

    if (dim4 == 192) {
        constexpr int RPB = 4;
        const int ngroups = (rows + RPB - 1) / RPB;          // 4096

        // One-wave persistent grid (host-side queries; capture-legal).
        int dev = 0, sms = 148, bpm = 8;
        cudaGetDevice(&dev);
        cudaDeviceGetAttribute(&sms, cudaDevAttrMultiProcessorCount, dev);
        cudaOccupancyMaxActiveBlocksPerMultiprocessor(
            &bpm, qembed_persist_kernel<192, RPB>, 192, 0);
        if (bpm < 1) bpm = 1;
        int grid = sms * bpm;
        if (grid > ngroups) grid = ngroups;
        if (grid < 1) grid = 1;

        qembed_persist_kernel<192, RPB><<<grid, 192>>>(
            x, (const float4*)w, pp, cp, (float4*)d_out,
            rows, ngroups, scalar_base, n_scalars);
    } else if ((dim % 4) == 0 && dim4 > 0) {
        int threads = dim4 < 256 ? ((dim4 + 31) / 32) * 32 : 256;
        if (threads < 32) threads = 32;
        qembed_row_kernel<<<rows, threads>>>(
            x, (const float4*)w, pp, cp, (float4*)d_out,
            dim4, scalar_base, n_scalars);
    }
}

// round 8
// speedup vs baseline: 1.5737x; 1.0022x over previous
#include <cuda_runtime.h>
#include <stdint.h>

// QuantEmbedding fused: out[0:rows*dim] = gather(QIL_quantize(W,p,c), x),
// out[rows*dim] = s = 127/(c-p), out[rows*dim+1] = p = max(pp,0).
//
// Persistent one-wave kernel. Block = 192 threads (= dim4), group = 4 rows,
// thread tid <-> float4 tid of each row (warp-contiguous, MLP=4), next-group
// token-id prefetch. Weight reads use DEFAULT caching (the ~43MB unique
// gathered row set fits in L2 and persists across graph replays; duplicates
// within an iteration also hit). Writes stay evict-first (__stcs) so the
// 50MB output stream does not displace the read set.

__device__ __forceinline__ float qil_one(float w, float p, float s, float inv_s) {
    // |w|<p => (|w|-p)*s < 0 => q <= 0, folded into the q>0 select.
    float aw = fabsf(w);
    float q  = rintf(fminf((aw - p) * s, 127.0f));
    float r  = copysignf(fmaf(q, inv_s, p), w);
    return (q > 0.0f) ? r : 0.0f;
}

__device__ __forceinline__ float4 qil_vec(float4 v, float p, float s, float inv_s) {
    float4 r;
    r.x = qil_one(v.x, p, s, inv_s);
    r.y = qil_one(v.y, p, s, inv_s);
    r.z = qil_one(v.z, p, s, inv_s);
    r.w = qil_one(v.w, p, s, inv_s);
    return r;
}

template <int DIM4, int RPB>
__global__ __launch_bounds__(DIM4)
void qembed_persist_kernel(const int* __restrict__ x,
                           const float4* __restrict__ w4,
                           const float* __restrict__ pp,
                           const float* __restrict__ cp,
                           float4* __restrict__ out4,
                           int rows, int ngroups,
                           long long scalar_base, int n_scalars) {
    const int tid = threadIdx.x;

    const float p = fmaxf(__ldg(&pp[0]), 0.0f);
    const float c = __ldg(&cp[0]);
    const float s = 127.0f / (c - p);
    const float inv_s = 1.0f / s;

    if (blockIdx.x == 0 && tid == 0 && n_scalars > 0) {
        float* out = (float*)out4;
        out[scalar_base] = s;
        if (n_scalars >= 2) out[scalar_base + 1] = p;
    }

    int g = blockIdx.x;

    // Prefetch token ids for the first group.
    int tok[RPB];
    if (g < ngroups) {
        const int row0 = g * RPB;
#pragma unroll
        for (int r = 0; r < RPB; r++)
            tok[r] = (row0 + r < rows) ? __ldg(&x[row0 + r]) : 0;
    }

    while (g < ngroups) {
        const int row0 = g * RPB;
        const int gn   = g + gridDim.x;

        // 4 independent coalesced row loads (MLP=4), DEFAULT caching:
        // L2-resident across replays + intra-iteration duplicate hits.
        float4 v[RPB];
#pragma unroll
        for (int r = 0; r < RPB; r++)
            v[r] = w4[(long long)tok[r] * DIM4 + tid];

        // Prefetch next group's token ids while row data is in flight.
        int tokn[RPB];
        if (gn < ngroups) {
            const int nrow0 = gn * RPB;
#pragma unroll
            for (int r = 0; r < RPB; r++)
                tokn[r] = (nrow0 + r < rows) ? __ldg(&x[nrow0 + r]) : 0;
        }

#pragma unroll
        for (int r = 0; r < RPB; r++) {
            if (row0 + r < rows)
                __stcs(&out4[(long long)(row0 + r) * DIM4 + tid],
                       qil_vec(v[r], p, s, inv_s));
        }

#pragma unroll
        for (int r = 0; r < RPB; r++) tok[r] = tokn[r];
        g = gn;
    }
}

// Generic fallback (arbitrary dim divisible by 4): one row per block.
__global__ __launch_bounds__(256)
void qembed_row_kernel(const int* __restrict__ x,
                       const float4* __restrict__ w4,
                       const float* __restrict__ pp,
                       const float* __restrict__ cp,
                       float4* __restrict__ out4,
                       int dim4, long long scalar_base, int n_scalars) {
    const int row = blockIdx.x;
    const int tok = __ldg(&x[row]);
    const float p = fmaxf(__ldg(&pp[0]), 0.0f);
    const float c = __ldg(&cp[0]);
    const float s = 127.0f / (c - p);
    const float inv_s = 1.0f / s;
    const long long src_base = (long long)tok * dim4;
    const long long dst_base = (long long)row * dim4;
    for (int j = threadIdx.x; j < dim4; j += blockDim.x) {
        float4 v = w4[src_base + j];
        __stcs(&out4[dst_base + j], qil_vec(v, p, s, inv_s));
    }
    if (blockIdx.x == 0 && threadIdx.x == 0 && n_scalars > 0) {
        float* out = (float*)out4;
        out[scalar_base] = s;
        if (n_scalars >= 2) out[scalar_base + 1] = p;
    }
}

extern "C" void kernel_launch(void* const* d_in, const int* in_sizes, int n_in,
                              void* d_out, int out_size) {
    const int*   x  = (const int*)d_in[0];          // [batch*seq] token ids
    const float* w  = (const float*)d_in[1];        // [vocab, dim] float32
    const float* pp = (const float*)d_in[2];        // [1]
    const float* cp = (const float*)d_in[3];        // [1]

    const int rows = in_sizes[0];                   // 16384

    // Derive dim and scalar-tail count from out_size.
    long long dim;
    int n_scalars;
    long long osz = (long long)out_size;
    if (rows > 0 && (osz - 2) > 0 && (osz - 2) % rows == 0) {
        dim = (osz - 2) / rows;  n_scalars = 2;     // expected: 768, 2
    } else if (rows > 0 && (osz - 1) > 0 && (osz - 1) % rows == 0) {
        dim = (osz - 1) / rows;  n_scalars = 1;
    } else {
        dim = (rows > 0) ? osz / rows : 0;  n_scalars = 0;
    }

    const int dim4 = (int)(dim / 4);
    const long long scalar_base = (long long)rows * dim;

    if (dim4 == 192) {
        constexpr int RPB = 4;
        const int ngroups = (rows + RPB - 1) / RPB;          // 4096

        // One-wave persistent grid (host-side queries; capture-legal).
        int dev = 0, sms = 148, bpm = 8;
        cudaGetDevice(&dev);
        cudaDeviceGetAttribute(&sms, cudaDevAttrMultiProcessorCount, dev);
        cudaOccupancyMaxActiveBlocksPerMultiprocessor(
            &bpm, qembed_persist_kernel<192, RPB>, 192, 0);
        if (bpm < 1) bpm = 1;
        int grid = sms * bpm;
        if (grid > ngroups) grid = ngroups;
        if (grid < 1) grid = 1;

        qembed_persist_kernel<192, RPB><<<grid, 192>>>(
            x, (const float4*)w, pp, cp, (float4*)d_out,
            rows, ngroups, scalar_base, n_scalars);
    } else if ((dim % 4) == 0 && dim4 > 0) {
        int threads = dim4 < 256 ? ((dim4 + 31) / 32) * 32 : 256;
        if (threads < 32) threads = 32;
        qembed_row_kernel<<<rows, threads>>>(
            x, (const float4*)w, pp, cp, (float4*)d_out,
            dim4, scalar_base, n_scalars);
    }
}